// round 12
// baseline (speedup 1.0000x reference)
#include <cuda_runtime.h>
#include <math.h>

// Problem constants
#define BATCH 8
#define SEQ 256
#define DMODEL 256
#define NHEADS 8
#define HDIM 32
#define ROWS (BATCH * SEQ)     // 2048

// Scratch (device globals — no allocation allowed)
__device__ float g_Qh[BATCH * NHEADS * SEQ * HDIM]; // [b,h,l,d]
__device__ float g_Kh[BATCH * NHEADS * SEQ * HDIM];
__device__ float g_Vh[BATCH * NHEADS * SEQ * HDIM];
__device__ float g_AO[ROWS * DMODEL];               // attention output, [b*l, dmodel]

// ---------------------------------------------------------------------------
// Fused Q/K/V projection. CTA tile 64x64, 256 threads, thread tile 4x4,
// K-tile 32. Smem stride 36 (16B aligned) + float4 smem reads along k:
// 8 LDS.128 per 64 FMA (4x fewer smem instructions than scalar layout).
// float4 global loads / STS.128 on the fill side, STG.128 on the store side.
// ---------------------------------------------------------------------------
__global__ __launch_bounds__(256) void gemm_proj3(
    const float* __restrict__ Q, const float* __restrict__ K,
    const float* __restrict__ V,
    const float* __restrict__ Wq, const float* __restrict__ bq,
    const float* __restrict__ Wk, const float* __restrict__ bk,
    const float* __restrict__ Wv, const float* __restrict__ bv,
    float* __restrict__ oQ, float* __restrict__ oK, float* __restrict__ oV)
{
    const float *X, *W, *bias;
    float* out;
    if (blockIdx.z == 0)      { X = Q; W = Wq; bias = bq; out = oQ; }
    else if (blockIdx.z == 1) { X = K; W = Wk; bias = bk; out = oK; }
    else                      { X = V; W = Wv; bias = bv; out = oV; }

    __shared__ float Xs[64][36];
    __shared__ float Ws[64][36];

    const int i0 = blockIdx.x * 64;
    const int j0 = blockIdx.y * 64;
    const int tid = threadIdx.x;
    const int tx = tid & 15;   // j direction
    const int ty = tid >> 4;   // i direction

    float acc[4][4];
#pragma unroll
    for (int m = 0; m < 4; m++)
#pragma unroll
        for (int n = 0; n < 4; n++) acc[m][n] = 0.f;

    for (int k0 = 0; k0 < DMODEL; k0 += 32) {
        // fill: 512 float4 per array, 2 per thread per array
#pragma unroll
        for (int t = 0; t < 2; t++) {
            int it = t * 256 + tid;
            int r = it >> 3;
            int c4 = (it & 7) * 4;
            *(float4*)&Xs[r][c4] =
                *(const float4*)(X + (size_t)(i0 + r) * DMODEL + k0 + c4);
            *(float4*)&Ws[r][c4] =
                *(const float4*)(W + (size_t)(j0 + r) * DMODEL + k0 + c4);
        }
        __syncthreads();
#pragma unroll
        for (int kk = 0; kk < 32; kk += 4) {
            float4 xr[4], wr[4];
#pragma unroll
            for (int m = 0; m < 4; m++) xr[m] = *(const float4*)&Xs[ty * 4 + m][kk];
#pragma unroll
            for (int n = 0; n < 4; n++) wr[n] = *(const float4*)&Ws[tx * 4 + n][kk];
#pragma unroll
            for (int m = 0; m < 4; m++)
#pragma unroll
                for (int n = 0; n < 4; n++) {
                    acc[m][n] = fmaf(xr[m].x, wr[n].x, acc[m][n]);
                    acc[m][n] = fmaf(xr[m].y, wr[n].y, acc[m][n]);
                    acc[m][n] = fmaf(xr[m].z, wr[n].z, acc[m][n]);
                    acc[m][n] = fmaf(xr[m].w, wr[n].w, acc[m][n]);
                }
        }
        __syncthreads();
    }

    // store: 4 consecutive j share a head -> contiguous float4 in [b,h,l,d]
    const int j = j0 + tx * 4;
    const float4 bj = *(const float4*)(bias + j);
    const int h = j >> 5;
    const int d0 = j & 31;
#pragma unroll
    for (int m = 0; m < 4; m++) {
        int i = i0 + ty * 4 + m;
        int b = i >> 8, q = i & 255;
        float4 v;
        v.x = acc[m][0] + bj.x;
        v.y = acc[m][1] + bj.y;
        v.z = acc[m][2] + bj.z;
        v.w = acc[m][3] + bj.w;
        *(float4*)(out + ((size_t)((b * NHEADS + h) * SEQ + q)) * HDIM + d0) = v;
    }
}

// ---------------------------------------------------------------------------
// Output projection: out = AO @ Wo^T + bo. Same vectorized body, plain store.
// ---------------------------------------------------------------------------
__global__ __launch_bounds__(256) void gemm_out(
    const float* __restrict__ X, const float* __restrict__ W,
    const float* __restrict__ bias, float* __restrict__ out)
{
    __shared__ float Xs[64][36];
    __shared__ float Ws[64][36];

    const int i0 = blockIdx.x * 64;
    const int j0 = blockIdx.y * 64;
    const int tid = threadIdx.x;
    const int tx = tid & 15;   // j direction
    const int ty = tid >> 4;   // i direction

    float acc[4][4];
#pragma unroll
    for (int m = 0; m < 4; m++)
#pragma unroll
        for (int n = 0; n < 4; n++) acc[m][n] = 0.f;

    for (int k0 = 0; k0 < DMODEL; k0 += 32) {
#pragma unroll
        for (int t = 0; t < 2; t++) {
            int it = t * 256 + tid;
            int r = it >> 3;
            int c4 = (it & 7) * 4;
            *(float4*)&Xs[r][c4] =
                *(const float4*)(X + (size_t)(i0 + r) * DMODEL + k0 + c4);
            *(float4*)&Ws[r][c4] =
                *(const float4*)(W + (size_t)(j0 + r) * DMODEL + k0 + c4);
        }
        __syncthreads();
#pragma unroll
        for (int kk = 0; kk < 32; kk += 4) {
            float4 xr[4], wr[4];
#pragma unroll
            for (int m = 0; m < 4; m++) xr[m] = *(const float4*)&Xs[ty * 4 + m][kk];
#pragma unroll
            for (int n = 0; n < 4; n++) wr[n] = *(const float4*)&Ws[tx * 4 + n][kk];
#pragma unroll
            for (int m = 0; m < 4; m++)
#pragma unroll
                for (int n = 0; n < 4; n++) {
                    acc[m][n] = fmaf(xr[m].x, wr[n].x, acc[m][n]);
                    acc[m][n] = fmaf(xr[m].y, wr[n].y, acc[m][n]);
                    acc[m][n] = fmaf(xr[m].z, wr[n].z, acc[m][n]);
                    acc[m][n] = fmaf(xr[m].w, wr[n].w, acc[m][n]);
                }
        }
        __syncthreads();
    }

    const int j = j0 + tx * 4;
    const float4 bj = *(const float4*)(bias + j);
#pragma unroll
    for (int m = 0; m < 4; m++) {
        int i = i0 + ty * 4 + m;
        float4 v;
        v.x = acc[m][0] + bj.x;
        v.y = acc[m][1] + bj.y;
        v.z = acc[m][2] + bj.z;
        v.w = acc[m][3] + bj.w;
        *(float4*)(out + (size_t)i * DMODEL + j) = v;
    }
}

// ---------------------------------------------------------------------------
// Attention kernel (R3-proven: 32 regs, occ ~85%, DRAM ~80%). Untouched.
// 1 CTA per (b,q). 8 warps, warp h handles head h. Streams tK/tV once.
// ---------------------------------------------------------------------------
__global__ __launch_bounds__(256) void attn_kernel(
    const float* __restrict__ tK, const float* __restrict__ tV)
{
    __shared__ float sc[NHEADS][SEQ];   // per-head scores / attention weights

    const int bq = blockIdx.x;          // b*256 + q
    const int b = bq >> 8;
    const int q = bq & 255;
    const int tid = threadIdx.x;
    const int h = tid >> 5;
    const int lane = tid & 31;
    const int kk = lane >> 3;           // 0..3
    const int dq = lane & 7;            // 0..7

    const float* __restrict__ tKb = tK + (size_t)bq * (SEQ * DMODEL);
    const float* __restrict__ tVb = tV + (size_t)bq * (SEQ * DMODEL);
    const float* __restrict__ KhB = g_Kh + (size_t)(b * NHEADS + h) * (SEQ * HDIM);
    const float* __restrict__ VhB = g_Vh + (size_t)(b * NHEADS + h) * (SEQ * HDIM);

    const float4 q4 = *(const float4*)(g_Qh +
        (size_t)((b * NHEADS + h) * SEQ + q) * HDIM + dq * 4);
    const float scale = 0.17677669529663687f;  // 1/sqrt(32)

    // ---- scores[k] = scale * q . (Kh[k] + tK[k]) ----
#pragma unroll 4
    for (int k0 = 0; k0 < SEQ; k0 += 4) {
        int k = k0 + kk;
        float4 t4 = *(const float4*)(tKb + (size_t)k * DMODEL + h * HDIM + dq * 4);
        float4 k4 = *(const float4*)(KhB + k * HDIM + dq * 4);
        float s = (t4.x + k4.x) * q4.x + (t4.y + k4.y) * q4.y
                + (t4.z + k4.z) * q4.z + (t4.w + k4.w) * q4.w;
        s += __shfl_xor_sync(0xffffffffu, s, 1);
        s += __shfl_xor_sync(0xffffffffu, s, 2);
        s += __shfl_xor_sync(0xffffffffu, s, 4);
        if (dq == 0) sc[h][k] = s * scale;
    }
    __syncwarp();

    // ---- softmax over k (per warp/head) ----
    float m = -1e30f;
#pragma unroll
    for (int i = lane; i < SEQ; i += 32) m = fmaxf(m, sc[h][i]);
#pragma unroll
    for (int o = 16; o; o >>= 1) m = fmaxf(m, __shfl_xor_sync(0xffffffffu, m, o));
    float sum = 0.f;
#pragma unroll
    for (int i = lane; i < SEQ; i += 32) {
        float e = __expf(sc[h][i] - m);
        sc[h][i] = e;
        sum += e;
    }
#pragma unroll
    for (int o = 16; o; o >>= 1) sum += __shfl_xor_sync(0xffffffffu, sum, o);
    const float inv = 1.f / sum;
#pragma unroll
    for (int i = lane; i < SEQ; i += 32) sc[h][i] *= inv;
    __syncwarp();

    // ---- out[d] = sum_k attn[k] * (Vh[k][d] + tV[k][d]) ----
    float4 acc = make_float4(0.f, 0.f, 0.f, 0.f);
#pragma unroll 4
    for (int k0 = 0; k0 < SEQ; k0 += 4) {
        int k = k0 + kk;
        float a = sc[h][k];
        float4 v4 = *(const float4*)(VhB + k * HDIM + dq * 4);
        float4 t4 = *(const float4*)(tVb + (size_t)k * DMODEL + h * HDIM + dq * 4);
        acc.x = fmaf(a, v4.x + t4.x, acc.x);
        acc.y = fmaf(a, v4.y + t4.y, acc.y);
        acc.z = fmaf(a, v4.z + t4.z, acc.z);
        acc.w = fmaf(a, v4.w + t4.w, acc.w);
    }
    // combine the 4 kk-groups (lanes dq, 8+dq, 16+dq, 24+dq)
    acc.x += __shfl_xor_sync(0xffffffffu, acc.x, 8);
    acc.y += __shfl_xor_sync(0xffffffffu, acc.y, 8);
    acc.z += __shfl_xor_sync(0xffffffffu, acc.z, 8);
    acc.w += __shfl_xor_sync(0xffffffffu, acc.w, 8);
    acc.x += __shfl_xor_sync(0xffffffffu, acc.x, 16);
    acc.y += __shfl_xor_sync(0xffffffffu, acc.y, 16);
    acc.z += __shfl_xor_sync(0xffffffffu, acc.z, 16);
    acc.w += __shfl_xor_sync(0xffffffffu, acc.w, 16);

    if (kk == 0) {
        *(float4*)(g_AO + (size_t)bq * DMODEL + h * HDIM + dq * 4) = acc;
    }
}

// ---------------------------------------------------------------------------
// Launch: fused QKV projection -> attention -> output GEMM. Single stream,
// no allocation, no sync — graph-capturable.
// ---------------------------------------------------------------------------
extern "C" void kernel_launch(void* const* d_in, const int* in_sizes, int n_in,
                              void* d_out, int out_size)
{
    const float* Q  = (const float*)d_in[0];
    const float* K  = (const float*)d_in[1];
    const float* V  = (const float*)d_in[2];
    const float* tK = (const float*)d_in[3];
    const float* tV = (const float*)d_in[4];
    const float* Wq = (const float*)d_in[5];
    const float* bq = (const float*)d_in[6];
    const float* Wk = (const float*)d_in[7];
    const float* bk = (const float*)d_in[8];
    const float* Wv = (const float*)d_in[9];
    const float* bv = (const float*)d_in[10];
    const float* Wo = (const float*)d_in[11];
    const float* bo = (const float*)d_in[12];
    float* out = (float*)d_out;

    float *gQh, *gKh, *gVh, *gAO;
    cudaGetSymbolAddress((void**)&gQh, g_Qh);
    cudaGetSymbolAddress((void**)&gKh, g_Kh);
    cudaGetSymbolAddress((void**)&gVh, g_Vh);
    cudaGetSymbolAddress((void**)&gAO, g_AO);

    dim3 pgrid(ROWS / 64, DMODEL / 64, 3);
    gemm_proj3<<<pgrid, 256>>>(Q, K, V, Wq, bq, Wk, bk, Wv, bv, gQh, gKh, gVh);

    attn_kernel<<<ROWS, 256>>>(tK, tV);

    dim3 ogrid(ROWS / 64, DMODEL / 64);
    gemm_out<<<ogrid, 256>>>(gAO, Wo, bo, out);
}

// round 15
// speedup vs baseline: 1.1549x; 1.1549x over previous
#include <cuda_runtime.h>
#include <math.h>

// Problem constants
#define BATCH 8
#define SEQ 256
#define DMODEL 256
#define NHEADS 8
#define HDIM 32
#define ROWS (BATCH * SEQ)     // 2048

// Scratch (device globals — no allocation allowed)
__device__ float g_Qh[BATCH * NHEADS * SEQ * HDIM]; // [b,h,l,d]
__device__ float g_Kh[BATCH * NHEADS * SEQ * HDIM];
__device__ float g_Vh[BATCH * NHEADS * SEQ * HDIM];
__device__ float g_AO[ROWS * DMODEL];               // attention output, [b*l, dmodel]

// XOR swizzle: element (r, c) lives at column c ^ SWZ(r). SWZ is a multiple
// of 4 so float4 groups stay contiguous. Conflict-free for both the
// 4-rows-per-warp fill and the tx/ty-strided LDS.128 compute reads.
#define SWZ(r) ((((r) >> 2) & 7) * 4)

// ---------------------------------------------------------------------------
// Fused Q/K/V projection. CTA tile 64x64, 256 threads, thread tile 4x4,
// K-tile 32. Swizzled smem (stride 32) + LDS.128 reads: 8 LDS.128 per 64 FMA,
// zero bank conflicts. float4 LDG/STS on fill, STG.128 on store.
// ---------------------------------------------------------------------------
__global__ __launch_bounds__(256) void gemm_proj3(
    const float* __restrict__ Q, const float* __restrict__ K,
    const float* __restrict__ V,
    const float* __restrict__ Wq, const float* __restrict__ bq,
    const float* __restrict__ Wk, const float* __restrict__ bk,
    const float* __restrict__ Wv, const float* __restrict__ bv,
    float* __restrict__ oQ, float* __restrict__ oK, float* __restrict__ oV)
{
    const float *X, *W, *bias;
    float* out;
    if (blockIdx.z == 0)      { X = Q; W = Wq; bias = bq; out = oQ; }
    else if (blockIdx.z == 1) { X = K; W = Wk; bias = bk; out = oK; }
    else                      { X = V; W = Wv; bias = bv; out = oV; }

    __shared__ float Xs[64][32];
    __shared__ float Ws[64][32];

    const int i0 = blockIdx.x * 64;
    const int j0 = blockIdx.y * 64;
    const int tid = threadIdx.x;
    const int tx = tid & 15;   // j direction
    const int ty = tid >> 4;   // i direction
    const int swx = (ty & 7) * 4;   // swizzle for Xs reads (rows ty*4+m)
    const int sww = (tx & 7) * 4;   // swizzle for Ws reads (rows tx*4+n)

    float acc[4][4];
#pragma unroll
    for (int m = 0; m < 4; m++)
#pragma unroll
        for (int n = 0; n < 4; n++) acc[m][n] = 0.f;

    for (int k0 = 0; k0 < DMODEL; k0 += 32) {
        // fill: 512 float4 per array, 2 per thread per array
#pragma unroll
        for (int t = 0; t < 2; t++) {
            int it = t * 256 + tid;
            int r = it >> 3;
            int c4 = (it & 7) * 4;
            int cs = c4 ^ SWZ(r);
            *(float4*)&Xs[r][cs] =
                *(const float4*)(X + (size_t)(i0 + r) * DMODEL + k0 + c4);
            *(float4*)&Ws[r][cs] =
                *(const float4*)(W + (size_t)(j0 + r) * DMODEL + k0 + c4);
        }
        __syncthreads();
#pragma unroll
        for (int kk = 0; kk < 32; kk += 4) {
            float4 xr[4], wr[4];
#pragma unroll
            for (int m = 0; m < 4; m++) xr[m] = *(const float4*)&Xs[ty * 4 + m][kk ^ swx];
#pragma unroll
            for (int n = 0; n < 4; n++) wr[n] = *(const float4*)&Ws[tx * 4 + n][kk ^ sww];
#pragma unroll
            for (int m = 0; m < 4; m++)
#pragma unroll
                for (int n = 0; n < 4; n++) {
                    acc[m][n] = fmaf(xr[m].x, wr[n].x, acc[m][n]);
                    acc[m][n] = fmaf(xr[m].y, wr[n].y, acc[m][n]);
                    acc[m][n] = fmaf(xr[m].z, wr[n].z, acc[m][n]);
                    acc[m][n] = fmaf(xr[m].w, wr[n].w, acc[m][n]);
                }
        }
        __syncthreads();
    }

    // store: 4 consecutive j share a head -> contiguous float4 in [b,h,l,d]
    const int j = j0 + tx * 4;
    const float4 bj = *(const float4*)(bias + j);
    const int h = j >> 5;
    const int d0 = j & 31;
#pragma unroll
    for (int m = 0; m < 4; m++) {
        int i = i0 + ty * 4 + m;
        int b = i >> 8, q = i & 255;
        float4 v;
        v.x = acc[m][0] + bj.x;
        v.y = acc[m][1] + bj.y;
        v.z = acc[m][2] + bj.z;
        v.w = acc[m][3] + bj.w;
        *(float4*)(out + ((size_t)((b * NHEADS + h) * SEQ + q)) * HDIM + d0) = v;
    }
}

// ---------------------------------------------------------------------------
// Output projection: out = AO @ Wo^T + bo. Same swizzled body, plain store.
// ---------------------------------------------------------------------------
__global__ __launch_bounds__(256) void gemm_out(
    const float* __restrict__ X, const float* __restrict__ W,
    const float* __restrict__ bias, float* __restrict__ out)
{
    __shared__ float Xs[64][32];
    __shared__ float Ws[64][32];

    const int i0 = blockIdx.x * 64;
    const int j0 = blockIdx.y * 64;
    const int tid = threadIdx.x;
    const int tx = tid & 15;   // j direction
    const int ty = tid >> 4;   // i direction
    const int swx = (ty & 7) * 4;
    const int sww = (tx & 7) * 4;

    float acc[4][4];
#pragma unroll
    for (int m = 0; m < 4; m++)
#pragma unroll
        for (int n = 0; n < 4; n++) acc[m][n] = 0.f;

    for (int k0 = 0; k0 < DMODEL; k0 += 32) {
#pragma unroll
        for (int t = 0; t < 2; t++) {
            int it = t * 256 + tid;
            int r = it >> 3;
            int c4 = (it & 7) * 4;
            int cs = c4 ^ SWZ(r);
            *(float4*)&Xs[r][cs] =
                *(const float4*)(X + (size_t)(i0 + r) * DMODEL + k0 + c4);
            *(float4*)&Ws[r][cs] =
                *(const float4*)(W + (size_t)(j0 + r) * DMODEL + k0 + c4);
        }
        __syncthreads();
#pragma unroll
        for (int kk = 0; kk < 32; kk += 4) {
            float4 xr[4], wr[4];
#pragma unroll
            for (int m = 0; m < 4; m++) xr[m] = *(const float4*)&Xs[ty * 4 + m][kk ^ swx];
#pragma unroll
            for (int n = 0; n < 4; n++) wr[n] = *(const float4*)&Ws[tx * 4 + n][kk ^ sww];
#pragma unroll
            for (int m = 0; m < 4; m++)
#pragma unroll
                for (int n = 0; n < 4; n++) {
                    acc[m][n] = fmaf(xr[m].x, wr[n].x, acc[m][n]);
                    acc[m][n] = fmaf(xr[m].y, wr[n].y, acc[m][n]);
                    acc[m][n] = fmaf(xr[m].z, wr[n].z, acc[m][n]);
                    acc[m][n] = fmaf(xr[m].w, wr[n].w, acc[m][n]);
                }
        }
        __syncthreads();
    }

    const int j = j0 + tx * 4;
    const float4 bj = *(const float4*)(bias + j);
#pragma unroll
    for (int m = 0; m < 4; m++) {
        int i = i0 + ty * 4 + m;
        float4 v;
        v.x = acc[m][0] + bj.x;
        v.y = acc[m][1] + bj.y;
        v.z = acc[m][2] + bj.z;
        v.w = acc[m][3] + bj.w;
        *(float4*)(out + (size_t)i * DMODEL + j) = v;
    }
}

// ---------------------------------------------------------------------------
// Attention kernel (R3-proven: 32 regs, occ ~85%, DRAM ~80%). Untouched.
// 1 CTA per (b,q). 8 warps, warp h handles head h. Streams tK/tV once.
// ---------------------------------------------------------------------------
__global__ __launch_bounds__(256) void attn_kernel(
    const float* __restrict__ tK, const float* __restrict__ tV)
{
    __shared__ float sc[NHEADS][SEQ];   // per-head scores / attention weights

    const int bq = blockIdx.x;          // b*256 + q
    const int b = bq >> 8;
    const int q = bq & 255;
    const int tid = threadIdx.x;
    const int h = tid >> 5;
    const int lane = tid & 31;
    const int kk = lane >> 3;           // 0..3
    const int dq = lane & 7;            // 0..7

    const float* __restrict__ tKb = tK + (size_t)bq * (SEQ * DMODEL);
    const float* __restrict__ tVb = tV + (size_t)bq * (SEQ * DMODEL);
    const float* __restrict__ KhB = g_Kh + (size_t)(b * NHEADS + h) * (SEQ * HDIM);
    const float* __restrict__ VhB = g_Vh + (size_t)(b * NHEADS + h) * (SEQ * HDIM);

    const float4 q4 = *(const float4*)(g_Qh +
        (size_t)((b * NHEADS + h) * SEQ + q) * HDIM + dq * 4);
    const float scale = 0.17677669529663687f;  // 1/sqrt(32)

    // ---- scores[k] = scale * q . (Kh[k] + tK[k]) ----
#pragma unroll 4
    for (int k0 = 0; k0 < SEQ; k0 += 4) {
        int k = k0 + kk;
        float4 t4 = *(const float4*)(tKb + (size_t)k * DMODEL + h * HDIM + dq * 4);
        float4 k4 = *(const float4*)(KhB + k * HDIM + dq * 4);
        float s = (t4.x + k4.x) * q4.x + (t4.y + k4.y) * q4.y
                + (t4.z + k4.z) * q4.z + (t4.w + k4.w) * q4.w;
        s += __shfl_xor_sync(0xffffffffu, s, 1);
        s += __shfl_xor_sync(0xffffffffu, s, 2);
        s += __shfl_xor_sync(0xffffffffu, s, 4);
        if (dq == 0) sc[h][k] = s * scale;
    }
    __syncwarp();

    // ---- softmax over k (per warp/head) ----
    float m = -1e30f;
#pragma unroll
    for (int i = lane; i < SEQ; i += 32) m = fmaxf(m, sc[h][i]);
#pragma unroll
    for (int o = 16; o; o >>= 1) m = fmaxf(m, __shfl_xor_sync(0xffffffffu, m, o));
    float sum = 0.f;
#pragma unroll
    for (int i = lane; i < SEQ; i += 32) {
        float e = __expf(sc[h][i] - m);
        sc[h][i] = e;
        sum += e;
    }
#pragma unroll
    for (int o = 16; o; o >>= 1) sum += __shfl_xor_sync(0xffffffffu, sum, o);
    const float inv = 1.f / sum;
#pragma unroll
    for (int i = lane; i < SEQ; i += 32) sc[h][i] *= inv;
    __syncwarp();

    // ---- out[d] = sum_k attn[k] * (Vh[k][d] + tV[k][d]) ----
    float4 acc = make_float4(0.f, 0.f, 0.f, 0.f);
#pragma unroll 4
    for (int k0 = 0; k0 < SEQ; k0 += 4) {
        int k = k0 + kk;
        float a = sc[h][k];
        float4 v4 = *(const float4*)(VhB + k * HDIM + dq * 4);
        float4 t4 = *(const float4*)(tVb + (size_t)k * DMODEL + h * HDIM + dq * 4);
        acc.x = fmaf(a, v4.x + t4.x, acc.x);
        acc.y = fmaf(a, v4.y + t4.y, acc.y);
        acc.z = fmaf(a, v4.z + t4.z, acc.z);
        acc.w = fmaf(a, v4.w + t4.w, acc.w);
    }
    // combine the 4 kk-groups (lanes dq, 8+dq, 16+dq, 24+dq)
    acc.x += __shfl_xor_sync(0xffffffffu, acc.x, 8);
    acc.y += __shfl_xor_sync(0xffffffffu, acc.y, 8);
    acc.z += __shfl_xor_sync(0xffffffffu, acc.z, 8);
    acc.w += __shfl_xor_sync(0xffffffffu, acc.w, 8);
    acc.x += __shfl_xor_sync(0xffffffffu, acc.x, 16);
    acc.y += __shfl_xor_sync(0xffffffffu, acc.y, 16);
    acc.z += __shfl_xor_sync(0xffffffffu, acc.z, 16);
    acc.w += __shfl_xor_sync(0xffffffffu, acc.w, 16);

    if (kk == 0) {
        *(float4*)(g_AO + (size_t)bq * DMODEL + h * HDIM + dq * 4) = acc;
    }
}

// ---------------------------------------------------------------------------
// Launch: fused QKV projection -> attention -> output GEMM. Single stream,
// no allocation, no sync — graph-capturable.
// ---------------------------------------------------------------------------
extern "C" void kernel_launch(void* const* d_in, const int* in_sizes, int n_in,
                              void* d_out, int out_size)
{
    const float* Q  = (const float*)d_in[0];
    const float* K  = (const float*)d_in[1];
    const float* V  = (const float*)d_in[2];
    const float* tK = (const float*)d_in[3];
    const float* tV = (const float*)d_in[4];
    const float* Wq = (const float*)d_in[5];
    const float* bq = (const float*)d_in[6];
    const float* Wk = (const float*)d_in[7];
    const float* bk = (const float*)d_in[8];
    const float* Wv = (const float*)d_in[9];
    const float* bv = (const float*)d_in[10];
    const float* Wo = (const float*)d_in[11];
    const float* bo = (const float*)d_in[12];
    float* out = (float*)d_out;

    float *gQh, *gKh, *gVh, *gAO;
    cudaGetSymbolAddress((void**)&gQh, g_Qh);
    cudaGetSymbolAddress((void**)&gKh, g_Kh);
    cudaGetSymbolAddress((void**)&gVh, g_Vh);
    cudaGetSymbolAddress((void**)&gAO, g_AO);

    dim3 pgrid(ROWS / 64, DMODEL / 64, 3);
    gemm_proj3<<<pgrid, 256>>>(Q, K, V, Wq, bq, Wk, bk, Wv, bv, gQh, gKh, gVh);

    attn_kernel<<<ROWS, 256>>>(tK, tV);

    dim3 ogrid(ROWS / 64, DMODEL / 64);
    gemm_out<<<ogrid, 256>>>(gAO, Wo, bo, out);
}

// round 16
// speedup vs baseline: 1.1772x; 1.0192x over previous
#include <cuda_runtime.h>
#include <math.h>

// Problem constants
#define BATCH 8
#define SEQ 256
#define DMODEL 256
#define NHEADS 8
#define HDIM 32
#define ROWS (BATCH * SEQ)     // 2048

// Scratch (device globals — no allocation allowed)
__device__ float g_Qh[BATCH * NHEADS * SEQ * HDIM]; // [b,h,l,d]
__device__ float g_Kh[BATCH * NHEADS * SEQ * HDIM];
__device__ float g_Vh[BATCH * NHEADS * SEQ * HDIM];
__device__ float g_AO[ROWS * DMODEL];               // attention output, [b*l, dmodel]

// ---------------------------------------------------------------------------
// Fused Q/K/V projection (R11 measured-best: 35us). blockIdx.z selects the
// projection. CTA tile 64x64, 256 threads, thread tile 4x4, K-tile 32,
// smem stride 33. Body written directly; head-split store hard-coded.
// ---------------------------------------------------------------------------
__global__ __launch_bounds__(256) void gemm_proj3(
    const float* __restrict__ Q, const float* __restrict__ K,
    const float* __restrict__ V,
    const float* __restrict__ Wq, const float* __restrict__ bq,
    const float* __restrict__ Wk, const float* __restrict__ bk,
    const float* __restrict__ Wv, const float* __restrict__ bv,
    float* __restrict__ oQ, float* __restrict__ oK, float* __restrict__ oV)
{
    const float *X, *W, *bias;
    float* out;
    if (blockIdx.z == 0)      { X = Q; W = Wq; bias = bq; out = oQ; }
    else if (blockIdx.z == 1) { X = K; W = Wk; bias = bk; out = oK; }
    else                      { X = V; W = Wv; bias = bv; out = oV; }

    __shared__ float Xs[64][33];
    __shared__ float Ws[64][33];

    const int i0 = blockIdx.x * 64;
    const int j0 = blockIdx.y * 64;
    const int tid = threadIdx.x;
    const int tx = tid & 15;   // j direction
    const int ty = tid >> 4;   // i direction

    float acc[4][4];
#pragma unroll
    for (int m = 0; m < 4; m++)
#pragma unroll
        for (int n = 0; n < 4; n++) acc[m][n] = 0.f;

    for (int k0 = 0; k0 < DMODEL; k0 += 32) {
#pragma unroll
        for (int i = tid; i < 64 * 32; i += 256) {
            int r = i >> 5, c = i & 31;
            Xs[r][c] = X[(size_t)(i0 + r) * DMODEL + k0 + c];
            Ws[r][c] = W[(size_t)(j0 + r) * DMODEL + k0 + c];
        }
        __syncthreads();
#pragma unroll
        for (int kk = 0; kk < 32; kk++) {
            float xr[4], wr[4];
#pragma unroll
            for (int m = 0; m < 4; m++) xr[m] = Xs[ty * 4 + m][kk];
#pragma unroll
            for (int n = 0; n < 4; n++) wr[n] = Ws[tx * 4 + n][kk];
#pragma unroll
            for (int m = 0; m < 4; m++)
#pragma unroll
                for (int n = 0; n < 4; n++)
                    acc[m][n] = fmaf(xr[m], wr[n], acc[m][n]);
        }
        __syncthreads();
    }

#pragma unroll
    for (int m = 0; m < 4; m++) {
#pragma unroll
        for (int n = 0; n < 4; n++) {
            int i = i0 + ty * 4 + m;
            int j = j0 + tx * 4 + n;
            float v = acc[m][n] + bias[j];
            int b = i >> 8, q = i & 255;
            int h = j >> 5, d = j & 31;
            out[((size_t)((b * NHEADS + h) * SEQ + q)) * HDIM + d] = v;
        }
    }
}

// ---------------------------------------------------------------------------
// Output projection: out = AO @ Wo^T + bo. Own inline body, plain [i][j] store.
// ---------------------------------------------------------------------------
__global__ __launch_bounds__(256) void gemm_out(
    const float* __restrict__ X, const float* __restrict__ W,
    const float* __restrict__ bias, float* __restrict__ out)
{
    __shared__ float Xs[64][33];
    __shared__ float Ws[64][33];

    const int i0 = blockIdx.x * 64;
    const int j0 = blockIdx.y * 64;
    const int tid = threadIdx.x;
    const int tx = tid & 15;   // j direction
    const int ty = tid >> 4;   // i direction

    float acc[4][4];
#pragma unroll
    for (int m = 0; m < 4; m++)
#pragma unroll
        for (int n = 0; n < 4; n++) acc[m][n] = 0.f;

    for (int k0 = 0; k0 < DMODEL; k0 += 32) {
#pragma unroll
        for (int i = tid; i < 64 * 32; i += 256) {
            int r = i >> 5, c = i & 31;
            Xs[r][c] = X[(size_t)(i0 + r) * DMODEL + k0 + c];
            Ws[r][c] = W[(size_t)(j0 + r) * DMODEL + k0 + c];
        }
        __syncthreads();
#pragma unroll
        for (int kk = 0; kk < 32; kk++) {
            float xr[4], wr[4];
#pragma unroll
            for (int m = 0; m < 4; m++) xr[m] = Xs[ty * 4 + m][kk];
#pragma unroll
            for (int n = 0; n < 4; n++) wr[n] = Ws[tx * 4 + n][kk];
#pragma unroll
            for (int m = 0; m < 4; m++)
#pragma unroll
                for (int n = 0; n < 4; n++)
                    acc[m][n] = fmaf(xr[m], wr[n], acc[m][n]);
        }
        __syncthreads();
    }

#pragma unroll
    for (int m = 0; m < 4; m++) {
#pragma unroll
        for (int n = 0; n < 4; n++) {
            int i = i0 + ty * 4 + m;
            int j = j0 + tx * 4 + n;
            out[(size_t)i * DMODEL + j] = acc[m][n] + bias[j];
        }
    }
}

// ---------------------------------------------------------------------------
// Attention kernel: R3 body with unroll 8 on the two streaming loops
// (more in-flight LDGs -> higher DRAM efficiency). 1 CTA per (b,q),
// 8 warps, warp h handles head h. Streams tK/tV once, coalesced.
// ---------------------------------------------------------------------------
__global__ __launch_bounds__(256) void attn_kernel(
    const float* __restrict__ tK, const float* __restrict__ tV)
{
    __shared__ float sc[NHEADS][SEQ];   // per-head scores / attention weights

    const int bq = blockIdx.x;          // b*256 + q
    const int b = bq >> 8;
    const int q = bq & 255;
    const int tid = threadIdx.x;
    const int h = tid >> 5;
    const int lane = tid & 31;
    const int kk = lane >> 3;           // 0..3
    const int dq = lane & 7;            // 0..7

    const float* __restrict__ tKb = tK + (size_t)bq * (SEQ * DMODEL);
    const float* __restrict__ tVb = tV + (size_t)bq * (SEQ * DMODEL);
    const float* __restrict__ KhB = g_Kh + (size_t)(b * NHEADS + h) * (SEQ * HDIM);
    const float* __restrict__ VhB = g_Vh + (size_t)(b * NHEADS + h) * (SEQ * HDIM);

    const float4 q4 = *(const float4*)(g_Qh +
        (size_t)((b * NHEADS + h) * SEQ + q) * HDIM + dq * 4);
    const float scale = 0.17677669529663687f;  // 1/sqrt(32)

    // ---- scores[k] = scale * q . (Kh[k] + tK[k]) ----
#pragma unroll 8
    for (int k0 = 0; k0 < SEQ; k0 += 4) {
        int k = k0 + kk;
        float4 t4 = *(const float4*)(tKb + (size_t)k * DMODEL + h * HDIM + dq * 4);
        float4 k4 = *(const float4*)(KhB + k * HDIM + dq * 4);
        float s = (t4.x + k4.x) * q4.x + (t4.y + k4.y) * q4.y
                + (t4.z + k4.z) * q4.z + (t4.w + k4.w) * q4.w;
        s += __shfl_xor_sync(0xffffffffu, s, 1);
        s += __shfl_xor_sync(0xffffffffu, s, 2);
        s += __shfl_xor_sync(0xffffffffu, s, 4);
        if (dq == 0) sc[h][k] = s * scale;
    }
    __syncwarp();

    // ---- softmax over k (per warp/head) ----
    float m = -1e30f;
#pragma unroll
    for (int i = lane; i < SEQ; i += 32) m = fmaxf(m, sc[h][i]);
#pragma unroll
    for (int o = 16; o; o >>= 1) m = fmaxf(m, __shfl_xor_sync(0xffffffffu, m, o));
    float sum = 0.f;
#pragma unroll
    for (int i = lane; i < SEQ; i += 32) {
        float e = __expf(sc[h][i] - m);
        sc[h][i] = e;
        sum += e;
    }
#pragma unroll
    for (int o = 16; o; o >>= 1) sum += __shfl_xor_sync(0xffffffffu, sum, o);
    const float inv = 1.f / sum;
#pragma unroll
    for (int i = lane; i < SEQ; i += 32) sc[h][i] *= inv;
    __syncwarp();

    // ---- out[d] = sum_k attn[k] * (Vh[k][d] + tV[k][d]) ----
    float4 acc = make_float4(0.f, 0.f, 0.f, 0.f);
#pragma unroll 8
    for (int k0 = 0; k0 < SEQ; k0 += 4) {
        int k = k0 + kk;
        float a = sc[h][k];
        float4 v4 = *(const float4*)(VhB + k * HDIM + dq * 4);
        float4 t4 = *(const float4*)(tVb + (size_t)k * DMODEL + h * HDIM + dq * 4);
        acc.x = fmaf(a, v4.x + t4.x, acc.x);
        acc.y = fmaf(a, v4.y + t4.y, acc.y);
        acc.z = fmaf(a, v4.z + t4.z, acc.z);
        acc.w = fmaf(a, v4.w + t4.w, acc.w);
    }
    // combine the 4 kk-groups (lanes dq, 8+dq, 16+dq, 24+dq)
    acc.x += __shfl_xor_sync(0xffffffffu, acc.x, 8);
    acc.y += __shfl_xor_sync(0xffffffffu, acc.y, 8);
    acc.z += __shfl_xor_sync(0xffffffffu, acc.z, 8);
    acc.w += __shfl_xor_sync(0xffffffffu, acc.w, 8);
    acc.x += __shfl_xor_sync(0xffffffffu, acc.x, 16);
    acc.y += __shfl_xor_sync(0xffffffffu, acc.y, 16);
    acc.z += __shfl_xor_sync(0xffffffffu, acc.z, 16);
    acc.w += __shfl_xor_sync(0xffffffffu, acc.w, 16);

    if (kk == 0) {
        *(float4*)(g_AO + (size_t)bq * DMODEL + h * HDIM + dq * 4) = acc;
    }
}

// ---------------------------------------------------------------------------
// Launch: fused QKV projection -> attention -> output GEMM. Single stream,
// no allocation, no sync — graph-capturable.
// ---------------------------------------------------------------------------
extern "C" void kernel_launch(void* const* d_in, const int* in_sizes, int n_in,
                              void* d_out, int out_size)
{
    const float* Q  = (const float*)d_in[0];
    const float* K  = (const float*)d_in[1];
    const float* V  = (const float*)d_in[2];
    const float* tK = (const float*)d_in[3];
    const float* tV = (const float*)d_in[4];
    const float* Wq = (const float*)d_in[5];
    const float* bq = (const float*)d_in[6];
    const float* Wk = (const float*)d_in[7];
    const float* bk = (const float*)d_in[8];
    const float* Wv = (const float*)d_in[9];
    const float* bv = (const float*)d_in[10];
    const float* Wo = (const float*)d_in[11];
    const float* bo = (const float*)d_in[12];
    float* out = (float*)d_out;

    float *gQh, *gKh, *gVh, *gAO;
    cudaGetSymbolAddress((void**)&gQh, g_Qh);
    cudaGetSymbolAddress((void**)&gKh, g_Kh);
    cudaGetSymbolAddress((void**)&gVh, g_Vh);
    cudaGetSymbolAddress((void**)&gAO, g_AO);

    dim3 pgrid(ROWS / 64, DMODEL / 64, 3);
    gemm_proj3<<<pgrid, 256>>>(Q, K, V, Wq, bq, Wk, bk, Wv, bv, gQh, gKh, gVh);

    attn_kernel<<<ROWS, 256>>>(tK, tV);

    dim3 ogrid(ROWS / 64, DMODEL / 64);
    gemm_out<<<ogrid, 256>>>(gAO, Wo, bo, out);
}